// round 15
// baseline (speedup 1.0000x reference)
#include <cuda_runtime.h>
#include <math.h>

#define Xd 32
#define Yd 16
#define Nn 8192          // 32*16*16
#define Cc 4
#define NITER 5
#define BETA  5.0f
#define DEG 4            // Taylor truncation (rel_err insensitive through DEG4)
#define RK 15            // #(i,j), i+j<=4
#define NTASK (RK * Cc + Cc)  // 64 conv tasks
#define NBLK (NTASK * 2)      // 128 blocks: 2 per task (input z-halves)

// shared layout (float offsets)
#define O_IN  0                 // 4096: input half field, idx = line*8 + zl
#define O_CX  4096              // 4352: conv-x out, idx = x*136 + y*8 + zl
#define O_CY  8448              // 5632: conv-y out, idx = (x*16+y)*11 + zl
#define O_CZ  14080             // 8704: conv-z out (full), idx = line*17 + z
#define O_TBL 22784
#define SMEM_FLOATS (22784 + 32)
#define SMEM_BYTES (SMEM_FLOATS * 4)

// Gaussian taps exp(-d*d/50) for ALPHA == GAMMA == 5.0 (compile-time constants)
__device__ constexpr float WT[32] = {
    1.000000000f, 0.980198673f, 0.923116346f, 0.835270211f,
    0.726149037f, 0.606530660f, 0.486752256f, 0.375311099f,
    0.278037300f, 0.197898699f, 0.135335283f, 0.0889216175f,
    0.0561347628f, 0.0340474547f, 0.0198410947f, 0.0111089965f,
    0.00597602290f, 0.00308871541f, 0.00153381068f, 0.000731802419f,
    0.000335462628f, 0.000147747400f, 6.25215038e-5f, 2.54193465e-5f,
    9.92950431e-6f, 3.72665317e-6f, 1.34381228e-6f, 4.65571000e-7f,
    1.54976000e-7f, 4.95642000e-8f, 1.52299797e-8f, 4.49638000e-9f
};

__host__ __device__ constexpr int cabs(int v) { return v < 0 ? -v : v; }

// ---- static device scratch ----
__device__ float g_phi[RK][Nn];      // immutable after phase A
__device__ float g_e[Nn];
__device__ float g_pre1[Nn];
__device__ float g_pre2[Nn];
__device__ float g_part[NBLK][Nn];   // per-block partial planes
__device__ float g_q[2][Cc][Nn];
__device__ unsigned g_arr[NBLK];
__device__ unsigned g_gen;

// ---- observer grid barrier (proven) ----
__device__ __forceinline__ void gbar(unsigned tgt, int b, int tid) {
    __syncthreads();
    if (b == 0) {
        if (tid == 0) { __threadfence(); *(volatile unsigned*)&g_arr[0] = tgt; }
        if (tid < NBLK) { while (*(volatile unsigned*)&g_arr[tid] < tgt) { } }
        __syncthreads();
        if (tid == 0) { __threadfence(); *(volatile unsigned*)&g_gen = tgt; }
    } else {
        if (tid == 0) {
            __threadfence();
            *(volatile unsigned*)&g_arr[b] = tgt;
            while (*(volatile unsigned*)&g_gen < tgt) { }
            __threadfence();
        }
        __syncthreads();
    }
}

// ==== template-recursive conv steps (R14-proven, unchanged) ====
template<int XG, int XP> struct CXs {
    static __device__ __forceinline__ void run(const float* sI, int pos, float* a) {
        float v = sI[(XP << 7) + pos];
        a[0] += WT[cabs(XG + 0 - XP)] * v;
        a[1] += WT[cabs(XG + 1 - XP)] * v;
        a[2] += WT[cabs(XG + 2 - XP)] * v;
        a[3] += WT[cabs(XG + 3 - XP)] * v;
        CXs<XG, XP + 1>::run(sI, pos, a);
    }
};
template<int XG> struct CXs<XG, 32> {
    static __device__ __forceinline__ void run(const float*, int, float*) {}
};
template<int XG>
__device__ __forceinline__ void conv_x_one(const float* sI, float* sX, int pos) {
    float a[4] = {0.f, 0.f, 0.f, 0.f};
    CXs<XG, 0>::run(sI, pos, a);
#pragma unroll
    for (int k = 0; k < 4; k++) sX[(XG + k) * 136 + pos] = a[k];
}
template<int YG, int YP> struct CYs {
    static __device__ __forceinline__ void run(const float* sX, int x, int zl, float* a) {
        float v = sX[x * 136 + (YP << 3) + zl];
        a[0] += WT[cabs(YG + 0 - YP)] * v;
        a[1] += WT[cabs(YG + 1 - YP)] * v;
        a[2] += WT[cabs(YG + 2 - YP)] * v;
        a[3] += WT[cabs(YG + 3 - YP)] * v;
        CYs<YG, YP + 1>::run(sX, x, zl, a);
    }
};
template<int YG> struct CYs<YG, 16> {
    static __device__ __forceinline__ void run(const float*, int, int, float*) {}
};
template<int YG>
__device__ __forceinline__ void conv_y_one(const float* sX, float* sY, int x, int zl) {
    float a[4] = {0.f, 0.f, 0.f, 0.f};
    CYs<YG, 0>::run(sX, x, zl, a);
#pragma unroll
    for (int k = 0; k < 4; k++) sY[(x * 16 + YG + k) * 11 + zl] = a[k];
}
template<int ZB, int ZL> struct CZs {
    static __device__ __forceinline__ void run(const float* in, float* a) {
        float v = in[ZL];
        a[0] += WT[cabs(ZB + 0 - ZL)] * v;
        a[1] += WT[cabs(ZB + 1 - ZL)] * v;
        a[2] += WT[cabs(ZB + 2 - ZL)] * v;
        a[3] += WT[cabs(ZB + 3 - ZL)] * v;
        a[4] += WT[cabs(ZB + 4 - ZL)] * v;
        a[5] += WT[cabs(ZB + 5 - ZL)] * v;
        a[6] += WT[cabs(ZB + 6 - ZL)] * v;
        a[7] += WT[cabs(ZB + 7 - ZL)] * v;
        CZs<ZB, ZL + 1>::run(in, a);
    }
};
template<int ZB> struct CZs<ZB, 8> {
    static __device__ __forceinline__ void run(const float*, float*) {}
};
template<int ZG, int ZB>
__device__ __forceinline__ void conv_z_one(const float* sY, float* sZ, int line) {
    float a[8] = {0.f,0.f,0.f,0.f,0.f,0.f,0.f,0.f};
    CZs<ZB, 0>::run(sY + line * 11, a);
#pragma unroll
    for (int k = 0; k < 8; k++) sZ[line * 17 + ZG + k] = a[k];
}

// ---- half-input separable conv (R14-proven) ----
__device__ __forceinline__ void conv3d_half(float* sm, int h, int tid) {
    float* sI = sm + O_IN;
    float* sX = sm + O_CX;
    float* sY = sm + O_CY;
    float* sZ = sm + O_CZ;
    __syncthreads();
    {
        int pos = tid & 127;
        switch (tid >> 7) {
            case 0: conv_x_one<0 >(sI, sX, pos); break;
            case 1: conv_x_one<4 >(sI, sX, pos); break;
            case 2: conv_x_one<8 >(sI, sX, pos); break;
            case 3: conv_x_one<12>(sI, sX, pos); break;
            case 4: conv_x_one<16>(sI, sX, pos); break;
            case 5: conv_x_one<20>(sI, sX, pos); break;
            case 6: conv_x_one<24>(sI, sX, pos); break;
            default: conv_x_one<28>(sI, sX, pos); break;
        }
    }
    __syncthreads();
    {
        int pos = tid & 255;
        int x = pos >> 3, zl = pos & 7;
        switch (tid >> 8) {
            case 0: conv_y_one<0 >(sX, sY, x, zl); break;
            case 1: conv_y_one<4 >(sX, sY, x, zl); break;
            case 2: conv_y_one<8 >(sX, sY, x, zl); break;
            default: conv_y_one<12>(sX, sY, x, zl); break;
        }
    }
    __syncthreads();
    {
        int line = tid & 511;
        if (h == 0) {
            if (tid < 512) conv_z_one<0, 0>(sY, sZ, line);
            else           conv_z_one<8, 8>(sY, sZ, line);
        } else {
            if (tid < 512) conv_z_one<0, -8>(sY, sZ, line);
            else           conv_z_one<8, 0>(sY, sZ, line);
        }
    }
    __syncthreads();
}

#define CONVOUT(sm, n) ((sm)[O_CZ + ((n) >> 4) * 17 + ((n) & 15)])

__global__ __launch_bounds__(1024, 1) void k_crf(
    const float* __restrict__ lu, const float* __restrict__ fp,
    const float* __restrict__ comp, float* __restrict__ out) {
    extern __shared__ float sm[];
    float* s_cmp = sm + O_TBL;
    __shared__ unsigned s_base;

    int tid = threadIdx.x;
    int b = blockIdx.x;

    if (tid == 0) s_base = *(volatile unsigned*)&g_arr[b];
    if (tid < 16) s_cmp[tid] = comp[tid];
    __syncthreads();
    unsigned base = s_base, bk = 0;

    int task = b >> 1, h = b & 1;

    // ==== phase A || B ====
    if (b < 2 * RK) {
        // B: partial rowsum conv for rank (task), input half h
        int i = 0, rr = task;
        while (rr > DEG - i) { rr -= DEG - i + 1; i++; }
        int j = rr;
        float fi = 1.f, fj = 1.f;
        for (int t = 2; t <= i; t++) fi *= (float)t;
        for (int t = 2; t <= j; t++) fj *= (float)t;
        float coef = rsqrtf(fi * fj);
        {
            int line = tid >> 1, q4 = tid & 1;
            int n0 = ((line << 2) + (h << 1) + q4) << 2;
#pragma unroll
            for (int el = 0; el < 4; el++) {
                int n = n0 + el;
                float fa = fp[n] * (1.0f / BETA);
                float fb = fp[Nn + n] * (1.0f / BETA);
                float e = __expf(-0.5f * (fa * fa + fb * fb));
                float pa = 1.f, pb = 1.f;
                for (int t = 0; t < i; t++) pa *= fa;
                for (int t = 0; t < j; t++) pb *= fb;
                sm[O_IN + (line << 3) + (q4 << 2) + el] = coef * pa * pb * e;
            }
        }
        conv3d_half(sm, h, tid);
#pragma unroll
        for (int u = 0; u < 2; u++) {
            int n0 = (tid * 2 + u) << 2;
#pragma unroll
            for (int el = 0; el < 4; el++) {
                int n = n0 + el;
                float fa = fp[n] * (1.0f / BETA);
                float fb = fp[Nn + n] * (1.0f / BETA);
                float pa = 1.f, pb = 1.f;
                for (int t = 0; t < i; t++) pa *= fa;
                for (int t = 0; t < j; t++) pb *= fb;
                g_part[b][n] = coef * pa * pb * CONVOUT(sm, n);
            }
        }
    } else if (b < 2 * RK + 8) {
        // A: phi basis, e, q0 — 8 full blocks, 1 voxel/thread
        int n = ((b - 2 * RK) << 10) + tid;
        float fa = fp[n] * (1.0f / BETA);
        float fb = fp[Nn + n] * (1.0f / BETA);
        float e = __expf(-0.5f * (fa * fa + fb * fb));
        g_e[n] = e;
        float fi = 1.f, pai = 1.f;
        int r = 0;
#pragma unroll
        for (int i = 0; i <= DEG; i++) {
            if (i > 0) fi *= (float)i;
            float fj = 1.f, pbj = 1.f;
#pragma unroll
            for (int j = 0; j <= DEG - i; j++) {
                if (j > 0) fj *= (float)j;
                g_phi[r][n] = rsqrtf(fi * fj) * pai * pbj;
                pbj *= fb;
                r++;
            }
            pai *= fa;
        }
        float l0 = lu[n], l1 = lu[Nn + n], l2 = lu[2 * Nn + n], l3 = lu[3 * Nn + n];
        float mx = fmaxf(fmaxf(l0, l1), fmaxf(l2, l3));
        float e0 = __expf(l0 - mx), e1 = __expf(l1 - mx);
        float e2 = __expf(l2 - mx), e3 = __expf(l3 - mx);
        float inv = 1.0f / (e0 + e1 + e2 + e3);
        g_q[0][0][n] = e0 * inv; g_q[0][1][n] = e1 * inv;
        g_q[0][2][n] = e2 * inv; g_q[0][3][n] = e3 * inv;
    }
    gbar(base + (++bk), b, tid);

    // ==== phase C: normalization scales ====
    if (b < 32 && tid < 256) {
        int n = (b << 8) + tid;
        float s = 0.f;
#pragma unroll
        for (int k = 0; k < 2 * RK; k++) s += __ldcg(&g_part[k][n]);
        float e = g_e[n];
        g_pre1[n] = e * rsqrtf(e * s);
        int x = n >> 8, y = (n >> 4) & 15, z = n & 15;
        float Rx = 0.f, Ry = 0.f, Rz = 0.f;
#pragma unroll
        for (int d = 0; d < Xd; d++) Rx += WT[(x > d) ? (x - d) : (d - x)];
#pragma unroll
        for (int d = 0; d < Yd; d++) {
            Ry += WT[(y > d) ? (y - d) : (d - y)];
            Rz += WT[(z > d) ? (z - d) : (d - z)];
        }
        g_pre2[n] = rsqrtf(Rx * Ry * Rz);
    }
    gbar(base + (++bk), b, tid);

    // ==== phase E: 5 mean-field iterations (pre1 folded on the fly) ====
    bool sp = (task >= RK * Cc);
    int r = sp ? 0 : (task >> 2);
    int c = sp ? (task - RK * Cc) : (task & 3);
    const float4* phi4  = (const float4*)g_phi[r];
    const float4* pre14 = (const float4*)g_pre1;
    const float4* pre24 = (const float4*)g_pre2;
    for (int it = 0; it < NITER; it++) {
        {
            const float4* q4g = (const float4*)g_q[it & 1][c];
            {
                int line = tid >> 1, q4 = tid & 1;
                int gf4 = (line << 2) + (h << 1) + q4;
                float4 Q = __ldcg(q4g + gf4);
                float4 M;
                if (sp) M = pre24[gf4];
                else {
                    float4 A = phi4[gf4], P = pre14[gf4];
                    M = make_float4(A.x * P.x, A.y * P.y, A.z * P.z, A.w * P.w);
                }
                *(float4*)(sm + O_IN + (line << 3) + (q4 << 2)) =
                    make_float4(M.x * Q.x, M.y * Q.y, M.z * Q.z, M.w * Q.w);
            }
            conv3d_half(sm, h, tid);
            float4* dst = (float4*)g_part[b];
#pragma unroll
            for (int u = 0; u < 2; u++) {
                int i4 = tid * 2 + u;
                float4 M;
                if (sp) M = pre24[i4];
                else {
                    float4 A = phi4[i4], P = pre14[i4];
                    M = make_float4(A.x * P.x, A.y * P.y, A.z * P.z, A.w * P.w);
                }
                int n0 = i4 << 2;
                dst[i4] = make_float4(M.x * CONVOUT(sm, n0),
                                      M.y * CONVOUT(sm, n0 + 1),
                                      M.z * CONVOUT(sm, n0 + 2),
                                      M.w * CONVOUT(sm, n0 + 3));
            }
        }
        gbar(base + (++bk), b, tid);
        // ==== update: ALL 128 blocks, 64 voxels each; tid = ks*256 + c*64 + n64 ====
        {
            int n64 = tid & 63, uc = (tid >> 6) & 3, ks = tid >> 8;
            int un = (b << 6) + n64;
            float u = 0.f;
#pragma unroll
            for (int m = 0; m < 8; m++) {
                int e = ks + (m << 2);         // entry 0..31
                int rr = e >> 1, hh = e & 1;
                int tk = (rr < RK) ? (rr * 4 + uc) : (RK * 4 + uc);
                u += __ldcg(&g_part[tk * 2 + hh][un]);
            }
            sm[O_IN + tid] = u;                // [ks][c][n64]
            __syncthreads();
            if (tid < 256) {
                float usum = sm[O_IN + tid] + sm[O_IN + tid + 256]
                           + sm[O_IN + tid + 512] + sm[O_IN + tid + 768];
                sm[O_CX + tid] = usum;         // [c][n64]
            }
            __syncthreads();
            if (tid < 256) {
                float u0 = sm[O_CX + 0 * 64 + n64], u1 = sm[O_CX + 1 * 64 + n64];
                float u2 = sm[O_CX + 2 * 64 + n64], u3 = sm[O_CX + 3 * 64 + n64];
                float lg0 = lu[un]          - (s_cmp[0] * u0 + s_cmp[1] * u1 + s_cmp[2] * u2 + s_cmp[3] * u3);
                float lg1 = lu[Nn + un]     - (s_cmp[4] * u0 + s_cmp[5] * u1 + s_cmp[6] * u2 + s_cmp[7] * u3);
                float lg2 = lu[2 * Nn + un] - (s_cmp[8] * u0 + s_cmp[9] * u1 + s_cmp[10] * u2 + s_cmp[11] * u3);
                float lg3 = lu[3 * Nn + un] - (s_cmp[12] * u0 + s_cmp[13] * u1 + s_cmp[14] * u2 + s_cmp[15] * u3);
                float mx = fmaxf(fmaxf(lg0, lg1), fmaxf(lg2, lg3));
                float e0 = __expf(lg0 - mx), e1 = __expf(lg1 - mx);
                float e2 = __expf(lg2 - mx), e3 = __expf(lg3 - mx);
                float inv = 1.0f / (e0 + e1 + e2 + e3);
                float qv = (uc == 0 ? e0 : uc == 1 ? e1 : uc == 2 ? e2 : e3) * inv;
                if (it == NITER - 1) out[uc * Nn + un] = qv;
                else                 g_q[(it + 1) & 1][uc][un] = qv;
            }
        }
        if (it < NITER - 1) gbar(base + (++bk), b, tid);
    }
}

extern "C" void kernel_launch(void* const* d_in, const int* in_sizes, int n_in,
                              void* d_out, int out_size) {
    const float* lu   = (const float*)d_in[0];
    const float* fp   = (const float*)d_in[1];
    const float* comp = (const float*)d_in[2];
    float* out = (float*)d_out;

    cudaFuncSetAttribute(k_crf, cudaFuncAttributeMaxDynamicSharedMemorySize, SMEM_BYTES);
    k_crf<<<NBLK, 1024, SMEM_BYTES>>>(lu, fp, comp, out);
}

// round 16
// speedup vs baseline: 1.1364x; 1.1364x over previous
#include <cuda_runtime.h>
#include <math.h>

#define Xd 32
#define Yd 16
#define Nn 8192          // 32*16*16
#define Cc 4
#define NITER 5
#define BETA  5.0f
#define DEG 4            // Taylor truncation (rel_err insensitive through DEG4)
#define RK 15            // #(i,j), i+j<=4
#define NTASK (RK * Cc + Cc)  // 64 conv tasks
#define NBLK (NTASK * 2)      // 128 blocks: 2 per task (input z-halves)

// shared layout (float offsets)
#define O_IN  0                 // 4096: input half field, idx = line*8 + zl
#define O_CX  4096              // 4352: conv-x out, idx = x*136 + y*8 + zl
#define O_CY  8448              // 5632: conv-y out, idx = (x*16+y)*11 + zl
#define O_CZ  14080             // 8704: conv-z out (full), idx = line*17 + z
#define O_TBL 22784
#define SMEM_FLOATS (22784 + 32)
#define SMEM_BYTES (SMEM_FLOATS * 4)

// Gaussian taps exp(-d*d/50) for ALPHA == GAMMA == 5.0 (compile-time constants)
__device__ constexpr float WT[32] = {
    1.000000000f, 0.980198673f, 0.923116346f, 0.835270211f,
    0.726149037f, 0.606530660f, 0.486752256f, 0.375311099f,
    0.278037300f, 0.197898699f, 0.135335283f, 0.0889216175f,
    0.0561347628f, 0.0340474547f, 0.0198410947f, 0.0111089965f,
    0.00597602290f, 0.00308871541f, 0.00153381068f, 0.000731802419f,
    0.000335462628f, 0.000147747400f, 6.25215038e-5f, 2.54193465e-5f,
    9.92950431e-6f, 3.72665317e-6f, 1.34381228e-6f, 4.65571000e-7f,
    1.54976000e-7f, 4.95642000e-8f, 1.52299797e-8f, 4.49638000e-9f
};

__host__ __device__ constexpr int cabs(int v) { return v < 0 ? -v : v; }

// ---- static device scratch ----
__device__ float g_phi[RK][Nn];      // immutable after phase A
__device__ float g_e[Nn];
__device__ float g_pre1[Nn];
__device__ float g_pre2[Nn];
__device__ float g_part[NBLK][Nn];   // per-block partial planes
__device__ float g_q[2][Cc][Nn];
__device__ unsigned g_arr[NBLK * 32];   // padded flags: one 128B line per block

// ---- single-hop symmetric barrier: padded flags, every block polls all ----
__device__ __forceinline__ void gbar(unsigned tgt, int b, int tid) {
    __syncthreads();
    if (tid == 0) { __threadfence(); *(volatile unsigned*)&g_arr[b * 32] = tgt; }
    if (tid < NBLK) {
        while (*(volatile unsigned*)&g_arr[tid * 32] < tgt) { }
    }
    __syncthreads();
}

// ==== template-recursive conv steps (R14-proven, unchanged) ====
template<int XG, int XP> struct CXs {
    static __device__ __forceinline__ void run(const float* sI, int pos, float* a) {
        float v = sI[(XP << 7) + pos];
        a[0] += WT[cabs(XG + 0 - XP)] * v;
        a[1] += WT[cabs(XG + 1 - XP)] * v;
        a[2] += WT[cabs(XG + 2 - XP)] * v;
        a[3] += WT[cabs(XG + 3 - XP)] * v;
        CXs<XG, XP + 1>::run(sI, pos, a);
    }
};
template<int XG> struct CXs<XG, 32> {
    static __device__ __forceinline__ void run(const float*, int, float*) {}
};
template<int XG>
__device__ __forceinline__ void conv_x_one(const float* sI, float* sX, int pos) {
    float a[4] = {0.f, 0.f, 0.f, 0.f};
    CXs<XG, 0>::run(sI, pos, a);
#pragma unroll
    for (int k = 0; k < 4; k++) sX[(XG + k) * 136 + pos] = a[k];
}
template<int YG, int YP> struct CYs {
    static __device__ __forceinline__ void run(const float* sX, int x, int zl, float* a) {
        float v = sX[x * 136 + (YP << 3) + zl];
        a[0] += WT[cabs(YG + 0 - YP)] * v;
        a[1] += WT[cabs(YG + 1 - YP)] * v;
        a[2] += WT[cabs(YG + 2 - YP)] * v;
        a[3] += WT[cabs(YG + 3 - YP)] * v;
        CYs<YG, YP + 1>::run(sX, x, zl, a);
    }
};
template<int YG> struct CYs<YG, 16> {
    static __device__ __forceinline__ void run(const float*, int, int, float*) {}
};
template<int YG>
__device__ __forceinline__ void conv_y_one(const float* sX, float* sY, int x, int zl) {
    float a[4] = {0.f, 0.f, 0.f, 0.f};
    CYs<YG, 0>::run(sX, x, zl, a);
#pragma unroll
    for (int k = 0; k < 4; k++) sY[(x * 16 + YG + k) * 11 + zl] = a[k];
}
template<int ZB, int ZL> struct CZs {
    static __device__ __forceinline__ void run(const float* in, float* a) {
        float v = in[ZL];
        a[0] += WT[cabs(ZB + 0 - ZL)] * v;
        a[1] += WT[cabs(ZB + 1 - ZL)] * v;
        a[2] += WT[cabs(ZB + 2 - ZL)] * v;
        a[3] += WT[cabs(ZB + 3 - ZL)] * v;
        a[4] += WT[cabs(ZB + 4 - ZL)] * v;
        a[5] += WT[cabs(ZB + 5 - ZL)] * v;
        a[6] += WT[cabs(ZB + 6 - ZL)] * v;
        a[7] += WT[cabs(ZB + 7 - ZL)] * v;
        CZs<ZB, ZL + 1>::run(in, a);
    }
};
template<int ZB> struct CZs<ZB, 8> {
    static __device__ __forceinline__ void run(const float*, float*) {}
};
template<int ZG, int ZB>
__device__ __forceinline__ void conv_z_one(const float* sY, float* sZ, int line) {
    float a[8] = {0.f,0.f,0.f,0.f,0.f,0.f,0.f,0.f};
    CZs<ZB, 0>::run(sY + line * 11, a);
#pragma unroll
    for (int k = 0; k < 8; k++) sZ[line * 17 + ZG + k] = a[k];
}

// ---- half-input separable conv (R14-proven) ----
__device__ __forceinline__ void conv3d_half(float* sm, int h, int tid) {
    float* sI = sm + O_IN;
    float* sX = sm + O_CX;
    float* sY = sm + O_CY;
    float* sZ = sm + O_CZ;
    __syncthreads();
    {
        int pos = tid & 127;
        switch (tid >> 7) {
            case 0: conv_x_one<0 >(sI, sX, pos); break;
            case 1: conv_x_one<4 >(sI, sX, pos); break;
            case 2: conv_x_one<8 >(sI, sX, pos); break;
            case 3: conv_x_one<12>(sI, sX, pos); break;
            case 4: conv_x_one<16>(sI, sX, pos); break;
            case 5: conv_x_one<20>(sI, sX, pos); break;
            case 6: conv_x_one<24>(sI, sX, pos); break;
            default: conv_x_one<28>(sI, sX, pos); break;
        }
    }
    __syncthreads();
    {
        int pos = tid & 255;
        int x = pos >> 3, zl = pos & 7;
        switch (tid >> 8) {
            case 0: conv_y_one<0 >(sX, sY, x, zl); break;
            case 1: conv_y_one<4 >(sX, sY, x, zl); break;
            case 2: conv_y_one<8 >(sX, sY, x, zl); break;
            default: conv_y_one<12>(sX, sY, x, zl); break;
        }
    }
    __syncthreads();
    {
        int line = tid & 511;
        if (h == 0) {
            if (tid < 512) conv_z_one<0, 0>(sY, sZ, line);
            else           conv_z_one<8, 8>(sY, sZ, line);
        } else {
            if (tid < 512) conv_z_one<0, -8>(sY, sZ, line);
            else           conv_z_one<8, 0>(sY, sZ, line);
        }
    }
    __syncthreads();
}

#define CONVOUT(sm, n) ((sm)[O_CZ + ((n) >> 4) * 17 + ((n) & 15)])

__global__ __launch_bounds__(1024, 1) void k_crf(
    const float* __restrict__ lu, const float* __restrict__ fp,
    const float* __restrict__ comp, float* __restrict__ out) {
    extern __shared__ float sm[];
    float* s_cmp = sm + O_TBL;
    __shared__ unsigned s_base;

    int tid = threadIdx.x;
    int b = blockIdx.x;

    if (tid == 0) s_base = *(volatile unsigned*)&g_arr[b * 32];  // own flag: replay-safe
    if (tid < 16) s_cmp[tid] = comp[tid];
    __syncthreads();
    unsigned base = s_base, bk = 0;

    int task = b >> 1, h = b & 1;

    // ==== phase A || B || pre2 (one wave) ====
    if (b < 2 * RK) {
        // B: partial rowsum conv for rank (task), input half h
        int i = 0, rr = task;
        while (rr > DEG - i) { rr -= DEG - i + 1; i++; }
        int j = rr;
        float fi = 1.f, fj = 1.f;
        for (int t = 2; t <= i; t++) fi *= (float)t;
        for (int t = 2; t <= j; t++) fj *= (float)t;
        float coef = rsqrtf(fi * fj);
        {
            int line = tid >> 1, q4 = tid & 1;
            int n0 = ((line << 2) + (h << 1) + q4) << 2;
#pragma unroll
            for (int el = 0; el < 4; el++) {
                int n = n0 + el;
                float fa = fp[n] * (1.0f / BETA);
                float fb = fp[Nn + n] * (1.0f / BETA);
                float e = __expf(-0.5f * (fa * fa + fb * fb));
                float pa = 1.f, pb = 1.f;
                for (int t = 0; t < i; t++) pa *= fa;
                for (int t = 0; t < j; t++) pb *= fb;
                sm[O_IN + (line << 3) + (q4 << 2) + el] = coef * pa * pb * e;
            }
        }
        conv3d_half(sm, h, tid);
#pragma unroll
        for (int u = 0; u < 2; u++) {
            int n0 = (tid * 2 + u) << 2;
#pragma unroll
            for (int el = 0; el < 4; el++) {
                int n = n0 + el;
                float fa = fp[n] * (1.0f / BETA);
                float fb = fp[Nn + n] * (1.0f / BETA);
                float pa = 1.f, pb = 1.f;
                for (int t = 0; t < i; t++) pa *= fa;
                for (int t = 0; t < j; t++) pb *= fb;
                g_part[b][n] = coef * pa * pb * CONVOUT(sm, n);
            }
        }
    } else if (b < 2 * RK + 8) {
        // A: phi basis, e, q0 — 8 full blocks, 1 voxel/thread
        int n = ((b - 2 * RK) << 10) + tid;
        float fa = fp[n] * (1.0f / BETA);
        float fb = fp[Nn + n] * (1.0f / BETA);
        float e = __expf(-0.5f * (fa * fa + fb * fb));
        g_e[n] = e;
        float fi = 1.f, pai = 1.f;
        int r = 0;
#pragma unroll
        for (int i = 0; i <= DEG; i++) {
            if (i > 0) fi *= (float)i;
            float fj = 1.f, pbj = 1.f;
#pragma unroll
            for (int j = 0; j <= DEG - i; j++) {
                if (j > 0) fj *= (float)j;
                g_phi[r][n] = rsqrtf(fi * fj) * pai * pbj;
                pbj *= fb;
                r++;
            }
            pai *= fa;
        }
        float l0 = lu[n], l1 = lu[Nn + n], l2 = lu[2 * Nn + n], l3 = lu[3 * Nn + n];
        float mx = fmaxf(fmaxf(l0, l1), fmaxf(l2, l3));
        float e0 = __expf(l0 - mx), e1 = __expf(l1 - mx);
        float e2 = __expf(l2 - mx), e3 = __expf(l3 - mx);
        float inv = 1.0f / (e0 + e1 + e2 + e3);
        g_q[0][0][n] = e0 * inv; g_q[0][1][n] = e1 * inv;
        g_q[0][2][n] = e2 * inv; g_q[0][3][n] = e3 * inv;
    } else if (b < 2 * RK + 8 + 32) {
        // pre2: spatial normalization (independent of B) — 32 blocks x 256 threads
        if (tid < 256) {
            int n = ((b - (2 * RK + 8)) << 8) + tid;
            int x = n >> 8, y = (n >> 4) & 15, z = n & 15;
            float Rx = 0.f, Ry = 0.f, Rz = 0.f;
#pragma unroll
            for (int d = 0; d < Xd; d++) Rx += WT[(x > d) ? (x - d) : (d - x)];
#pragma unroll
            for (int d = 0; d < Yd; d++) {
                Ry += WT[(y > d) ? (y - d) : (d - y)];
                Rz += WT[(z > d) ? (z - d) : (d - z)];
            }
            g_pre2[n] = rsqrtf(Rx * Ry * Rz);
        }
    }
    gbar(base + (++bk), b, tid);

    // ==== phase C: pre1 only ====
    if (b < 32 && tid < 256) {
        int n = (b << 8) + tid;
        float s = 0.f;
#pragma unroll
        for (int k = 0; k < 2 * RK; k++) s += __ldcg(&g_part[k][n]);
        float e = g_e[n];
        g_pre1[n] = e * rsqrtf(e * s);
    }
    gbar(base + (++bk), b, tid);

    // ==== phase E: 5 mean-field iterations (pre1 folded on the fly) ====
    bool sp = (task >= RK * Cc);
    int r = sp ? 0 : (task >> 2);
    int c = sp ? (task - RK * Cc) : (task & 3);
    const float4* phi4  = (const float4*)g_phi[r];
    const float4* pre14 = (const float4*)g_pre1;
    const float4* pre24 = (const float4*)g_pre2;
    // hoisted update-phase state (R14-proven layout)
    int uc = 0, un = 0, ulv = 0;
    if (b < 32) {
        int warp = tid >> 5, lane = tid & 31;
        uc = warp & 3;
        ulv = ((warp >> 2) << 5) + lane;
        un = (b << 8) + ulv;
    }
    for (int it = 0; it < NITER; it++) {
        {
            const float4* q4g = (const float4*)g_q[it & 1][c];
            {
                int line = tid >> 1, q4 = tid & 1;
                int gf4 = (line << 2) + (h << 1) + q4;
                float4 Q = __ldcg(q4g + gf4);
                float4 M;
                if (sp) M = pre24[gf4];
                else {
                    float4 A = phi4[gf4], P = pre14[gf4];
                    M = make_float4(A.x * P.x, A.y * P.y, A.z * P.z, A.w * P.w);
                }
                *(float4*)(sm + O_IN + (line << 3) + (q4 << 2)) =
                    make_float4(M.x * Q.x, M.y * Q.y, M.z * Q.z, M.w * Q.w);
            }
            conv3d_half(sm, h, tid);
            float4* dst = (float4*)g_part[b];
#pragma unroll
            for (int u = 0; u < 2; u++) {
                int i4 = tid * 2 + u;
                float4 M;
                if (sp) M = pre24[i4];
                else {
                    float4 A = phi4[i4], P = pre14[i4];
                    M = make_float4(A.x * P.x, A.y * P.y, A.z * P.z, A.w * P.w);
                }
                int n0 = i4 << 2;
                dst[i4] = make_float4(M.x * CONVOUT(sm, n0),
                                      M.y * CONVOUT(sm, n0 + 1),
                                      M.z * CONVOUT(sm, n0 + 2),
                                      M.w * CONVOUT(sm, n0 + 3));
            }
        }
        gbar(base + (++bk), b, tid);
        // ==== update (R14-proven): 32 blocks, warp-coalesced k-sweep ====
        if (b < 32) {
            float u = 0.f;
#pragma unroll
            for (int rr = 0; rr < RK; rr++) {
                u += __ldcg(&g_part[(rr * 4 + uc) * 2 + 0][un]);
                u += __ldcg(&g_part[(rr * 4 + uc) * 2 + 1][un]);
            }
            u += __ldcg(&g_part[(RK * 4 + uc) * 2 + 0][un]);
            u += __ldcg(&g_part[(RK * 4 + uc) * 2 + 1][un]);
            sm[O_IN + uc * 256 + ulv] = u;
            __syncthreads();
            float u0 = sm[O_IN + 0 * 256 + ulv], u1 = sm[O_IN + 1 * 256 + ulv];
            float u2 = sm[O_IN + 2 * 256 + ulv], u3 = sm[O_IN + 3 * 256 + ulv];
            float lg0 = lu[un]          - (s_cmp[0] * u0 + s_cmp[1] * u1 + s_cmp[2] * u2 + s_cmp[3] * u3);
            float lg1 = lu[Nn + un]     - (s_cmp[4] * u0 + s_cmp[5] * u1 + s_cmp[6] * u2 + s_cmp[7] * u3);
            float lg2 = lu[2 * Nn + un] - (s_cmp[8] * u0 + s_cmp[9] * u1 + s_cmp[10] * u2 + s_cmp[11] * u3);
            float lg3 = lu[3 * Nn + un] - (s_cmp[12] * u0 + s_cmp[13] * u1 + s_cmp[14] * u2 + s_cmp[15] * u3);
            float mx = fmaxf(fmaxf(lg0, lg1), fmaxf(lg2, lg3));
            float e0 = __expf(lg0 - mx), e1 = __expf(lg1 - mx);
            float e2 = __expf(lg2 - mx), e3 = __expf(lg3 - mx);
            float inv = 1.0f / (e0 + e1 + e2 + e3);
            float qv = (uc == 0 ? e0 : uc == 1 ? e1 : uc == 2 ? e2 : e3) * inv;
            if (it == NITER - 1) out[uc * Nn + un] = qv;
            else                 g_q[(it + 1) & 1][uc][un] = qv;
        }
        if (it < NITER - 1) gbar(base + (++bk), b, tid);
    }
}

extern "C" void kernel_launch(void* const* d_in, const int* in_sizes, int n_in,
                              void* d_out, int out_size) {
    const float* lu   = (const float*)d_in[0];
    const float* fp   = (const float*)d_in[1];
    const float* comp = (const float*)d_in[2];
    float* out = (float*)d_out;

    cudaFuncSetAttribute(k_crf, cudaFuncAttributeMaxDynamicSharedMemorySize, SMEM_BYTES);
    k_crf<<<NBLK, 1024, SMEM_BYTES>>>(lu, fp, comp, out);
}

// round 17
// speedup vs baseline: 1.1635x; 1.0238x over previous
#include <cuda_runtime.h>
#include <math.h>

#define Xd 32
#define Yd 16
#define Nn 8192          // 32*16*16
#define Cc 4
#define NITER 5
#define BETA  5.0f
#define DEG 4            // Taylor truncation (rel_err insensitive through DEG4)
#define RK 15            // #(i,j), i+j<=4
#define NTASK (RK * Cc + Cc)  // 64 conv tasks
#define NBLK (NTASK * 2)      // 128 blocks: 2 per task (input z-halves)
#define NUPD 32               // updater blocks

// shared layout (float offsets)
#define O_IN  0                 // 4096: input half field, idx = line*8 + zl
#define O_CX  4096              // 4352: conv-x out, idx = x*136 + y*8 + zl
#define O_CY  8448              // 5632: conv-y out, idx = (x*16+y)*11 + zl
#define O_CZ  14080             // 8704: conv-z out (full), idx = line*17 + z
#define O_TBL 22784
#define SMEM_FLOATS (22784 + 32)
#define SMEM_BYTES (SMEM_FLOATS * 4)

// Gaussian taps exp(-d*d/50) for ALPHA == GAMMA == 5.0 (compile-time constants)
__device__ constexpr float WT[32] = {
    1.000000000f, 0.980198673f, 0.923116346f, 0.835270211f,
    0.726149037f, 0.606530660f, 0.486752256f, 0.375311099f,
    0.278037300f, 0.197898699f, 0.135335283f, 0.0889216175f,
    0.0561347628f, 0.0340474547f, 0.0198410947f, 0.0111089965f,
    0.00597602290f, 0.00308871541f, 0.00153381068f, 0.000731802419f,
    0.000335462628f, 0.000147747400f, 6.25215038e-5f, 2.54193465e-5f,
    9.92950431e-6f, 3.72665317e-6f, 1.34381228e-6f, 4.65571000e-7f,
    1.54976000e-7f, 4.95642000e-8f, 1.52299797e-8f, 4.49638000e-9f
};

__host__ __device__ constexpr int cabs(int v) { return v < 0 ? -v : v; }

// ---- static device scratch ----
__device__ float g_phi[RK][Nn];      // immutable after phase A
__device__ float g_e[Nn];
__device__ float g_pre1[Nn];
__device__ float g_pre2[Nn];
__device__ float g_part[NBLK][Nn];   // per-block partial planes
__device__ float g_q[2][Cc][Nn];
__device__ unsigned g_arr[NBLK * 32];   // padded arrive flags (one 128B line each)
__device__ unsigned g_upd[NUPD * 32];   // padded update-done flags

// arrive: store own flag (no polling)
__device__ __forceinline__ void arrive(unsigned tgt, int b, int tid) {
    __syncthreads();
    if (tid == 0) { __threadfence(); *(volatile unsigned*)&g_arr[b * 32] = tgt; }
}
// updaters: poll all NBLK arrive flags
__device__ __forceinline__ void wait_all_arrive(unsigned tgt, int tid) {
    if (tid < NBLK) {
        while (*(volatile unsigned*)&g_arr[tid * 32] < tgt) { }
    }
    __syncthreads();
}
// updaters: publish update-done
__device__ __forceinline__ void publish_upd(unsigned tgt, int b, int tid) {
    __syncthreads();
    if (tid == 0) { __threadfence(); *(volatile unsigned*)&g_upd[b * 32] = tgt; }
}
// everyone: wait for all NUPD update flags
__device__ __forceinline__ void wait_upd(unsigned tgt, int tid) {
    if (tid < NUPD) {
        while (*(volatile unsigned*)&g_upd[tid * 32] < tgt) { }
    }
    __syncthreads();
}

// ==== template-recursive conv steps (R14-proven, unchanged) ====
template<int XG, int XP> struct CXs {
    static __device__ __forceinline__ void run(const float* sI, int pos, float* a) {
        float v = sI[(XP << 7) + pos];
        a[0] += WT[cabs(XG + 0 - XP)] * v;
        a[1] += WT[cabs(XG + 1 - XP)] * v;
        a[2] += WT[cabs(XG + 2 - XP)] * v;
        a[3] += WT[cabs(XG + 3 - XP)] * v;
        CXs<XG, XP + 1>::run(sI, pos, a);
    }
};
template<int XG> struct CXs<XG, 32> {
    static __device__ __forceinline__ void run(const float*, int, float*) {}
};
template<int XG>
__device__ __forceinline__ void conv_x_one(const float* sI, float* sX, int pos) {
    float a[4] = {0.f, 0.f, 0.f, 0.f};
    CXs<XG, 0>::run(sI, pos, a);
#pragma unroll
    for (int k = 0; k < 4; k++) sX[(XG + k) * 136 + pos] = a[k];
}
template<int YG, int YP> struct CYs {
    static __device__ __forceinline__ void run(const float* sX, int x, int zl, float* a) {
        float v = sX[x * 136 + (YP << 3) + zl];
        a[0] += WT[cabs(YG + 0 - YP)] * v;
        a[1] += WT[cabs(YG + 1 - YP)] * v;
        a[2] += WT[cabs(YG + 2 - YP)] * v;
        a[3] += WT[cabs(YG + 3 - YP)] * v;
        CYs<YG, YP + 1>::run(sX, x, zl, a);
    }
};
template<int YG> struct CYs<YG, 16> {
    static __device__ __forceinline__ void run(const float*, int, int, float*) {}
};
template<int YG>
__device__ __forceinline__ void conv_y_one(const float* sX, float* sY, int x, int zl) {
    float a[4] = {0.f, 0.f, 0.f, 0.f};
    CYs<YG, 0>::run(sX, x, zl, a);
#pragma unroll
    for (int k = 0; k < 4; k++) sY[(x * 16 + YG + k) * 11 + zl] = a[k];
}
template<int ZB, int ZL> struct CZs {
    static __device__ __forceinline__ void run(const float* in, float* a) {
        float v = in[ZL];
        a[0] += WT[cabs(ZB + 0 - ZL)] * v;
        a[1] += WT[cabs(ZB + 1 - ZL)] * v;
        a[2] += WT[cabs(ZB + 2 - ZL)] * v;
        a[3] += WT[cabs(ZB + 3 - ZL)] * v;
        a[4] += WT[cabs(ZB + 4 - ZL)] * v;
        a[5] += WT[cabs(ZB + 5 - ZL)] * v;
        a[6] += WT[cabs(ZB + 6 - ZL)] * v;
        a[7] += WT[cabs(ZB + 7 - ZL)] * v;
        CZs<ZB, ZL + 1>::run(in, a);
    }
};
template<int ZB> struct CZs<ZB, 8> {
    static __device__ __forceinline__ void run(const float*, float*) {}
};
template<int ZG, int ZB>
__device__ __forceinline__ void conv_z_one(const float* sY, float* sZ, int line) {
    float a[8] = {0.f,0.f,0.f,0.f,0.f,0.f,0.f,0.f};
    CZs<ZB, 0>::run(sY + line * 11, a);
#pragma unroll
    for (int k = 0; k < 8; k++) sZ[line * 17 + ZG + k] = a[k];
}

// ---- half-input separable conv (R14-proven) ----
__device__ __forceinline__ void conv3d_half(float* sm, int h, int tid) {
    float* sI = sm + O_IN;
    float* sX = sm + O_CX;
    float* sY = sm + O_CY;
    float* sZ = sm + O_CZ;
    __syncthreads();
    {
        int pos = tid & 127;
        switch (tid >> 7) {
            case 0: conv_x_one<0 >(sI, sX, pos); break;
            case 1: conv_x_one<4 >(sI, sX, pos); break;
            case 2: conv_x_one<8 >(sI, sX, pos); break;
            case 3: conv_x_one<12>(sI, sX, pos); break;
            case 4: conv_x_one<16>(sI, sX, pos); break;
            case 5: conv_x_one<20>(sI, sX, pos); break;
            case 6: conv_x_one<24>(sI, sX, pos); break;
            default: conv_x_one<28>(sI, sX, pos); break;
        }
    }
    __syncthreads();
    {
        int pos = tid & 255;
        int x = pos >> 3, zl = pos & 7;
        switch (tid >> 8) {
            case 0: conv_y_one<0 >(sX, sY, x, zl); break;
            case 1: conv_y_one<4 >(sX, sY, x, zl); break;
            case 2: conv_y_one<8 >(sX, sY, x, zl); break;
            default: conv_y_one<12>(sX, sY, x, zl); break;
        }
    }
    __syncthreads();
    {
        int line = tid & 511;
        if (h == 0) {
            if (tid < 512) conv_z_one<0, 0>(sY, sZ, line);
            else           conv_z_one<8, 8>(sY, sZ, line);
        } else {
            if (tid < 512) conv_z_one<0, -8>(sY, sZ, line);
            else           conv_z_one<8, 0>(sY, sZ, line);
        }
    }
    __syncthreads();
}

#define CONVOUT(sm, n) ((sm)[O_CZ + ((n) >> 4) * 17 + ((n) & 15)])

__global__ __launch_bounds__(1024, 1) void k_crf(
    const float* __restrict__ lu, const float* __restrict__ fp,
    const float* __restrict__ comp, float* __restrict__ out) {
    extern __shared__ float sm[];
    float* s_cmp = sm + O_TBL;
    __shared__ unsigned s_base, s_ubase;

    int tid = threadIdx.x;
    int b = blockIdx.x;

    if (tid == 0) {
        s_base  = *(volatile unsigned*)&g_arr[b * 32];  // own flag: replay-safe
        s_ubase = *(volatile unsigned*)&g_upd[0];       // uniform at launch boundary
    }
    if (tid < 16) s_cmp[tid] = comp[tid];
    __syncthreads();
    unsigned base = s_base, ubase = s_ubase;

    int task = b >> 1, h = b & 1;
    bool updater = (b < NUPD);

    // ==== wave 1: A || B || pre2 ====
    if (b < 2 * RK) {
        // B: partial rowsum conv for rank (task), input half h
        int i = 0, rr = task;
        while (rr > DEG - i) { rr -= DEG - i + 1; i++; }
        int j = rr;
        float fi = 1.f, fj = 1.f;
        for (int t = 2; t <= i; t++) fi *= (float)t;
        for (int t = 2; t <= j; t++) fj *= (float)t;
        float coef = rsqrtf(fi * fj);
        {
            int line = tid >> 1, q4 = tid & 1;
            int n0 = ((line << 2) + (h << 1) + q4) << 2;
#pragma unroll
            for (int el = 0; el < 4; el++) {
                int n = n0 + el;
                float fa = fp[n] * (1.0f / BETA);
                float fb = fp[Nn + n] * (1.0f / BETA);
                float e = __expf(-0.5f * (fa * fa + fb * fb));
                float pa = 1.f, pb = 1.f;
                for (int t = 0; t < i; t++) pa *= fa;
                for (int t = 0; t < j; t++) pb *= fb;
                sm[O_IN + (line << 3) + (q4 << 2) + el] = coef * pa * pb * e;
            }
        }
        conv3d_half(sm, h, tid);
#pragma unroll
        for (int u = 0; u < 2; u++) {
            int n0 = (tid * 2 + u) << 2;
#pragma unroll
            for (int el = 0; el < 4; el++) {
                int n = n0 + el;
                float fa = fp[n] * (1.0f / BETA);
                float fb = fp[Nn + n] * (1.0f / BETA);
                float pa = 1.f, pb = 1.f;
                for (int t = 0; t < i; t++) pa *= fa;
                for (int t = 0; t < j; t++) pb *= fb;
                g_part[b][n] = coef * pa * pb * CONVOUT(sm, n);
            }
        }
    } else if (b < 2 * RK + 8) {
        // A: phi basis, e, q0 — 8 full blocks, 1 voxel/thread
        int n = ((b - 2 * RK) << 10) + tid;
        float fa = fp[n] * (1.0f / BETA);
        float fb = fp[Nn + n] * (1.0f / BETA);
        float e = __expf(-0.5f * (fa * fa + fb * fb));
        g_e[n] = e;
        float fi = 1.f, pai = 1.f;
        int r = 0;
#pragma unroll
        for (int i = 0; i <= DEG; i++) {
            if (i > 0) fi *= (float)i;
            float fj = 1.f, pbj = 1.f;
#pragma unroll
            for (int j = 0; j <= DEG - i; j++) {
                if (j > 0) fj *= (float)j;
                g_phi[r][n] = rsqrtf(fi * fj) * pai * pbj;
                pbj *= fb;
                r++;
            }
            pai *= fa;
        }
        float l0 = lu[n], l1 = lu[Nn + n], l2 = lu[2 * Nn + n], l3 = lu[3 * Nn + n];
        float mx = fmaxf(fmaxf(l0, l1), fmaxf(l2, l3));
        float e0 = __expf(l0 - mx), e1 = __expf(l1 - mx);
        float e2 = __expf(l2 - mx), e3 = __expf(l3 - mx);
        float inv = 1.0f / (e0 + e1 + e2 + e3);
        g_q[0][0][n] = e0 * inv; g_q[0][1][n] = e1 * inv;
        g_q[0][2][n] = e2 * inv; g_q[0][3][n] = e3 * inv;
    } else if (b < 2 * RK + 8 + 32) {
        // pre2: spatial normalization — 32 blocks x 256 threads
        if (tid < 256) {
            int n = ((b - (2 * RK + 8)) << 8) + tid;
            int x = n >> 8, y = (n >> 4) & 15, z = n & 15;
            float Rx = 0.f, Ry = 0.f, Rz = 0.f;
#pragma unroll
            for (int d = 0; d < Xd; d++) Rx += WT[(x > d) ? (x - d) : (d - x)];
#pragma unroll
            for (int d = 0; d < Yd; d++) {
                Ry += WT[(y > d) ? (y - d) : (d - y)];
                Rz += WT[(z > d) ? (z - d) : (d - z)];
            }
            g_pre2[n] = rsqrtf(Rx * Ry * Rz);
        }
    }
    arrive(base + 1, b, tid);

    // ==== phase C (updater blocks only): pre1 ====
    if (updater) {
        wait_all_arrive(base + 1, tid);
        if (tid < 256) {
            int n = (b << 8) + tid;
            float s = 0.f;
#pragma unroll
            for (int k = 0; k < 2 * RK; k++) s += __ldcg(&g_part[k][n]);
            float e = g_e[n];
            g_pre1[n] = e * rsqrtf(e * s);
        }
        publish_upd(ubase + 1, b, tid);
    }
    wait_upd(ubase + 1, tid);

    // ==== phase E: 5 mean-field iterations (pre1 folded on the fly) ====
    bool sp = (task >= RK * Cc);
    int r = sp ? 0 : (task >> 2);
    int c = sp ? (task - RK * Cc) : (task & 3);
    const float4* phi4  = (const float4*)g_phi[r];
    const float4* pre14 = (const float4*)g_pre1;
    const float4* pre24 = (const float4*)g_pre2;
    // hoisted update-phase state (R14-proven layout)
    int uc = 0, un = 0, ulv = 0;
    if (updater) {
        int warp = tid >> 5, lane = tid & 31;
        uc = warp & 3;
        ulv = ((warp >> 2) << 5) + lane;
        un = (b << 8) + ulv;
    }
    for (int it = 0; it < NITER; it++) {
        {
            const float4* q4g = (const float4*)g_q[it & 1][c];
            {
                int line = tid >> 1, q4 = tid & 1;
                int gf4 = (line << 2) + (h << 1) + q4;
                float4 Q = __ldcg(q4g + gf4);
                float4 M;
                if (sp) M = pre24[gf4];
                else {
                    float4 A = phi4[gf4], P = pre14[gf4];
                    M = make_float4(A.x * P.x, A.y * P.y, A.z * P.z, A.w * P.w);
                }
                *(float4*)(sm + O_IN + (line << 3) + (q4 << 2)) =
                    make_float4(M.x * Q.x, M.y * Q.y, M.z * Q.z, M.w * Q.w);
            }
            conv3d_half(sm, h, tid);
            float4* dst = (float4*)g_part[b];
#pragma unroll
            for (int u = 0; u < 2; u++) {
                int i4 = tid * 2 + u;
                float4 M;
                if (sp) M = pre24[i4];
                else {
                    float4 A = phi4[i4], P = pre14[i4];
                    M = make_float4(A.x * P.x, A.y * P.y, A.z * P.z, A.w * P.w);
                }
                int n0 = i4 << 2;
                dst[i4] = make_float4(M.x * CONVOUT(sm, n0),
                                      M.y * CONVOUT(sm, n0 + 1),
                                      M.z * CONVOUT(sm, n0 + 2),
                                      M.w * CONVOUT(sm, n0 + 3));
            }
        }
        arrive(base + 2 + it, b, tid);
        // ==== update (updater blocks only) ====
        if (updater) {
            wait_all_arrive(base + 2 + it, tid);
            float u = 0.f;
#pragma unroll
            for (int rr = 0; rr < RK; rr++) {
                u += __ldcg(&g_part[(rr * 4 + uc) * 2 + 0][un]);
                u += __ldcg(&g_part[(rr * 4 + uc) * 2 + 1][un]);
            }
            u += __ldcg(&g_part[(RK * 4 + uc) * 2 + 0][un]);
            u += __ldcg(&g_part[(RK * 4 + uc) * 2 + 1][un]);
            sm[O_IN + uc * 256 + ulv] = u;
            __syncthreads();
            float u0 = sm[O_IN + 0 * 256 + ulv], u1 = sm[O_IN + 1 * 256 + ulv];
            float u2 = sm[O_IN + 2 * 256 + ulv], u3 = sm[O_IN + 3 * 256 + ulv];
            float lg0 = lu[un]          - (s_cmp[0] * u0 + s_cmp[1] * u1 + s_cmp[2] * u2 + s_cmp[3] * u3);
            float lg1 = lu[Nn + un]     - (s_cmp[4] * u0 + s_cmp[5] * u1 + s_cmp[6] * u2 + s_cmp[7] * u3);
            float lg2 = lu[2 * Nn + un] - (s_cmp[8] * u0 + s_cmp[9] * u1 + s_cmp[10] * u2 + s_cmp[11] * u3);
            float lg3 = lu[3 * Nn + un] - (s_cmp[12] * u0 + s_cmp[13] * u1 + s_cmp[14] * u2 + s_cmp[15] * u3);
            float mx = fmaxf(fmaxf(lg0, lg1), fmaxf(lg2, lg3));
            float e0 = __expf(lg0 - mx), e1 = __expf(lg1 - mx);
            float e2 = __expf(lg2 - mx), e3 = __expf(lg3 - mx);
            float inv = 1.0f / (e0 + e1 + e2 + e3);
            float qv = (uc == 0 ? e0 : uc == 1 ? e1 : uc == 2 ? e2 : e3) * inv;
            if (it == NITER - 1) {
                out[uc * Nn + un] = qv;
            } else {
                g_q[(it + 1) & 1][uc][un] = qv;
                publish_upd(ubase + 2 + it, b, tid);
            }
        }
        if (it < NITER - 1) wait_upd(ubase + 2 + it, tid);
    }
}

extern "C" void kernel_launch(void* const* d_in, const int* in_sizes, int n_in,
                              void* d_out, int out_size) {
    const float* lu   = (const float*)d_in[0];
    const float* fp   = (const float*)d_in[1];
    const float* comp = (const float*)d_in[2];
    float* out = (float*)d_out;

    cudaFuncSetAttribute(k_crf, cudaFuncAttributeMaxDynamicSharedMemorySize, SMEM_BYTES);
    k_crf<<<NBLK, 1024, SMEM_BYTES>>>(lu, fp, comp, out);
}